// round 13
// baseline (speedup 1.0000x reference)
#include <cuda_runtime.h>
#include <math.h>

// Problem constants
#define B_  2
#define L_  4096
#define D_  128
#define H_  4

// Scratch (allocation-free rule: __device__ globals)
__device__ float g_q[B_ * H_ * L_ * D_];
__device__ float g_k[B_ * H_ * L_ * D_];
__device__ float g_v[B_ * H_ * L_ * D_];
__device__ float g_ctx[B_ * L_ * H_ * D_];   // [b][l][h][e]

// ---------------------------------------------------------------------------
// tf32 helpers
// ---------------------------------------------------------------------------
__device__ __forceinline__ unsigned f2tf(float f) {
    unsigned r;
    asm("cvt.rna.tf32.f32 %0, %1;" : "=r"(r) : "f"(f));
    return r;
}

__device__ __forceinline__ void mma8(float d[4], const unsigned a[4],
                                     unsigned b0, unsigned b1) {
    asm volatile(
        "mma.sync.aligned.m16n8k8.row.col.f32.tf32.tf32.f32 "
        "{%0,%1,%2,%3}, {%4,%5,%6,%7}, {%8,%9}, {%0,%1,%2,%3};\n"
        : "+f"(d[0]), "+f"(d[1]), "+f"(d[2]), "+f"(d[3])
        : "r"(a[0]), "r"(a[1]), "r"(a[2]), "r"(a[3]), "r"(b0), "r"(b1));
}

__device__ __forceinline__ void cpa16(unsigned saddr, const void* g) {
    asm volatile("cp.async.cg.shared.global [%0], [%1], 16;"
                 :: "r"(saddr), "l"(g));
}
__device__ __forceinline__ void cpa_commit() {
    asm volatile("cp.async.commit_group;");
}
__device__ __forceinline__ void cpa_wait0() {
    asm volatile("cp.async.wait_group 0;");
}

// pi_128 permutation (GEMM staging): element c -> base + {0,8,16,24} within
//   base = (c>>6)*64 + ((c>>2)&1)*32 + ((c>>3)&7)
#define GSTR 132

// ---------------------------------------------------------------------------
// Kernel 1: QKV projections (unchanged from R10).  CTA tile 128m x 64n.
// ---------------------------------------------------------------------------
__global__ __launch_bounds__(256, 2) void qkv_kernel(
    const float* __restrict__ x,
    const float* __restrict__ Wq,
    const float* __restrict__ Wk,
    const float* __restrict__ Wv)
{
    extern __shared__ unsigned gsm[];
    unsigned* As = gsm;                // 128 * 132
    unsigned* Bs = As + 128 * GSTR;    // 64  * 132

    const float* W   = (blockIdx.z == 0) ? Wq : ((blockIdx.z == 1) ? Wk : Wv);
    float*       out = (blockIdx.z == 0) ? g_q : ((blockIdx.z == 1) ? g_k : g_v);

    const int t    = threadIdx.x;
    const int w    = t >> 5;
    const int lane = t & 31;
    const int rl   = lane >> 2;
    const int cl   = lane & 3;
    const int wm   = w & 3;
    const int wn   = w >> 2;
    const int m0   = blockIdx.x * 128;
    const int n0   = blockIdx.y * 64;

    for (int i = t; i < 4096; i += 256) {
        int row = i >> 5;
        int c4  = (i & 31) * 4;
        int base = row * GSTR + ((c4 >> 6) << 6) + (((c4 >> 2) & 1) << 5) + ((c4 >> 3) & 7);
        float4 xv = *(const float4*)(x + (size_t)(m0 + row) * D_ + c4);
        As[base]      = f2tf(xv.x);
        As[base + 8]  = f2tf(xv.y);
        As[base + 16] = f2tf(xv.z);
        As[base + 24] = f2tf(xv.w);
    }
    for (int i = t; i < 2048; i += 256) {
        int row = i >> 5;
        int c4  = (i & 31) * 4;
        int base = row * GSTR + ((c4 >> 6) << 6) + (((c4 >> 2) & 1) << 5) + ((c4 >> 3) & 7);
        float4 wv = *(const float4*)(W + (size_t)(n0 + row) * D_ + c4);
        Bs[base]      = f2tf(wv.x);
        Bs[base + 8]  = f2tf(wv.y);
        Bs[base + 16] = f2tf(wv.z);
        Bs[base + 24] = f2tf(wv.w);
    }
    __syncthreads();

    float acc[2][4][4];
#pragma unroll
    for (int mt = 0; mt < 2; mt++)
#pragma unroll
        for (int nt = 0; nt < 4; nt++)
#pragma unroll
            for (int c = 0; c < 4; c++) acc[mt][nt][c] = 0.f;

#pragma unroll
    for (int ktg = 0; ktg < 4; ktg++) {
        const int kbase = ((ktg >> 1) << 6) + ((ktg & 1) << 2) + cl * 8;
        uint4 a0[2], a1[2], a2[2], a3[2];
#pragma unroll
        for (int mt = 0; mt < 2; mt++) {
            int ar = (wm * 32 + mt * 16 + rl) * GSTR + kbase;
            a0[mt] = *(const uint4*)&As[ar];
            a2[mt] = *(const uint4*)&As[ar + 32];
            a1[mt] = *(const uint4*)&As[ar + 8 * GSTR];
            a3[mt] = *(const uint4*)&As[ar + 8 * GSTR + 32];
        }
#pragma unroll
        for (int nt = 0; nt < 4; nt++) {
            int br = (wn * 32 + nt * 8 + rl) * GSTR + kbase;
            uint4 b0 = *(const uint4*)&Bs[br];
            uint4 b1 = *(const uint4*)&Bs[br + 32];
#pragma unroll
            for (int mt = 0; mt < 2; mt++) {
                unsigned aa[4];
                aa[0] = a0[mt].x; aa[1] = a1[mt].x; aa[2] = a2[mt].x; aa[3] = a3[mt].x;
                mma8(acc[mt][nt], aa, b0.x, b1.x);
                aa[0] = a0[mt].y; aa[1] = a1[mt].y; aa[2] = a2[mt].y; aa[3] = a3[mt].y;
                mma8(acc[mt][nt], aa, b0.y, b1.y);
                aa[0] = a0[mt].z; aa[1] = a1[mt].z; aa[2] = a2[mt].z; aa[3] = a3[mt].z;
                mma8(acc[mt][nt], aa, b0.z, b1.z);
                aa[0] = a0[mt].w; aa[1] = a1[mt].w; aa[2] = a2[mt].w; aa[3] = a3[mt].w;
                mma8(acc[mt][nt], aa, b0.w, b1.w);
            }
        }
    }

    const int h = n0 >> 7;
#pragma unroll
    for (int mt = 0; mt < 2; mt++) {
        int m = m0 + wm * 32 + mt * 16 + rl;
        int b = m >> 12;
        int l = m & 4095;
        float* obase = out + (((size_t)b * H_ + h) * L_ + l) * D_;
#pragma unroll
        for (int nt = 0; nt < 4; nt++) {
            int n = n0 + wn * 32 + nt * 8 + 2 * cl;
            int e = n & 127;
            float2 lo; lo.x = acc[mt][nt][0]; lo.y = acc[mt][nt][1];
            float2 hi; hi.x = acc[mt][nt][2]; hi.y = acc[mt][nt][3];
            *(float2*)(obase + e) = lo;
            *(float2*)(obase + 8 * (size_t)D_ + e) = hi;
        }
    }
}

// ---------------------------------------------------------------------------
// Kernel 2: causal flash attention, tf32, cp.async pipeline, 2 CTAs/SM.
// grid = (L/64, B*H), block = 128 (4 warps; warp owns 16 q rows).
// smem (words), K/V rows at stride 136 (conflict-free fragment reads):
//   Kraw[2] : 2*64*136 = 17408  (double-buffered; raw fp32 as truncated tf32)
//   Vraw    : 64*136   = 8704   (single-buffered; rna cvt inline in registers)
// total 26112 words = 104,448 B  -> 2 CTAs/SM.
// P transposed S->A fragment layout via __shfl (no smem round-trip).
// ---------------------------------------------------------------------------
#define KSTRW 136
#define KP_OFF 0
#define VR_OFF (2 * 64 * KSTRW)
#define SM_WORDS (VR_OFF + 64 * KSTRW)

__global__ __launch_bounds__(128, 2) void attn_kernel()
{
    extern __shared__ unsigned sm[];
    unsigned smem_base = (unsigned)__cvta_generic_to_shared(sm);

    const int t    = threadIdx.x;
    const int w    = t >> 5;           // 0..3
    const int lane = t & 31;
    const int rl   = lane >> 2;        // 0..7
    const int cl   = lane & 3;         // 0..3
    const int qt   = (gridDim.x - 1) - blockIdx.x;   // heavy tiles first
    const int bh   = blockIdx.y;

    const float* qg = g_q + ((size_t)bh * L_ + (size_t)qt * 64) * D_;
    const float* kg = g_k + (size_t)bh * L_ * D_;
    const float* vg = g_v + (size_t)bh * L_ * D_;

    const int ntiles = qt + 1;

    // ---- prologue: cp.async K0 -> Kbuf0, V0 -> Vbuf ----
    {
#pragma unroll
        for (int j = 0; j < 16; j++) {
            int i = t + 128 * j;
            int row = i >> 5;
            int c4  = (i & 31) * 4;
            cpa16(smem_base + (unsigned)(KP_OFF + row * KSTRW + c4) * 4,
                  kg + (size_t)row * D_ + c4);
            cpa16(smem_base + (unsigned)(VR_OFF + row * KSTRW + c4) * 4,
                  vg + (size_t)row * D_ + c4);
        }
        cpa_commit();
    }

    // ---- Q A-fragments cached in registers (overlaps with cp.async) ----
    unsigned Qa[16][4];
    {
        const float* qw = qg + (size_t)(w * 16) * D_;
#pragma unroll
        for (int kt = 0; kt < 16; kt++) {
            Qa[kt][0] = f2tf(qw[(size_t)(rl)     * D_ + kt * 8 + cl]);
            Qa[kt][1] = f2tf(qw[(size_t)(rl + 8) * D_ + kt * 8 + cl]);
            Qa[kt][2] = f2tf(qw[(size_t)(rl)     * D_ + kt * 8 + 4 + cl]);
            Qa[kt][3] = f2tf(qw[(size_t)(rl + 8) * D_ + kt * 8 + 4 + cl]);
        }
    }

    float Oacc[16][4];
#pragma unroll
    for (int nt = 0; nt < 16; nt++)
#pragma unroll
        for (int c = 0; c < 4; c++) Oacc[nt][c] = 0.f;
    float m0 = -INFINITY, m1 = -INFINITY, l0 = 0.f, l1 = 0.f;

    const int qg0 = qt * 64 + w * 16 + rl;
    const int qg1 = qg0 + 8;

    const int src0 = 4 * rl + (cl >> 1);   // shfl source lanes for P transpose
    const int src1 = src0 + 2;
    const bool odd = (cl & 1);

    for (int kb = 0; kb < ntiles; ++kb) {
        cpa_wait0();          // K(kb) and V(kb) landed (this thread's groups)
        __syncthreads();      // visible to all; all warps done with prev tile

        const unsigned* Kp = sm + KP_OFF + (kb & 1) * (64 * KSTRW);
        const float*    Vr = (const float*)(sm + VR_OFF);

        // ---- issue cp.async K(kb+1) into the other K buffer ----
        if (kb + 1 < ntiles) {
            const float* kp = kg + (size_t)(kb + 1) * 64 * D_;
            unsigned kb32 = smem_base + (unsigned)(KP_OFF + ((kb + 1) & 1) * (64 * KSTRW)) * 4;
#pragma unroll
            for (int j = 0; j < 16; j++) {
                int i = t + 128 * j;
                int row = i >> 5;
                int c4  = (i & 31) * 4;
                cpa16(kb32 + (unsigned)(row * KSTRW + c4) * 4, kp + (size_t)row * D_ + c4);
            }
            cpa_commit();
        }

        // ---- S = Q K^T  (K raw fp32 bits as truncated tf32) ----
        float Sf[8][4];
#pragma unroll
        for (int nt = 0; nt < 8; nt++)
#pragma unroll
            for (int c = 0; c < 4; c++) Sf[nt][c] = 0.f;

#pragma unroll
        for (int kt = 0; kt < 16; kt++) {
#pragma unroll
            for (int nt = 0; nt < 8; nt++) {
                unsigned b0 = Kp[(nt * 8 + rl) * KSTRW + kt * 8 + cl];
                unsigned b1 = Kp[(nt * 8 + rl) * KSTRW + kt * 8 + 4 + cl];
                mma8(Sf[nt], Qa[kt], b0, b1);
            }
        }

        // ---- causal mask (diagonal tile only: kb == qt) ----
        if (kb == ntiles - 1) {
#pragma unroll
            for (int nt = 0; nt < 8; nt++) {
                int kgb = kb * 64 + nt * 8 + 2 * cl;
                if (kgb     > qg0) Sf[nt][0] = -INFINITY;
                if (kgb + 1 > qg0) Sf[nt][1] = -INFINITY;
                if (kgb     > qg1) Sf[nt][2] = -INFINITY;
                if (kgb + 1 > qg1) Sf[nt][3] = -INFINITY;
            }
        }

        // ---- online softmax: exp values stay in registers ----
        float mx0 = Sf[0][0], mx1 = Sf[0][2];
#pragma unroll
        for (int nt = 0; nt < 8; nt++) {
            mx0 = fmaxf(mx0, fmaxf(Sf[nt][0], Sf[nt][1]));
            mx1 = fmaxf(mx1, fmaxf(Sf[nt][2], Sf[nt][3]));
        }
        mx0 = fmaxf(mx0, __shfl_xor_sync(0xffffffffu, mx0, 1));
        mx0 = fmaxf(mx0, __shfl_xor_sync(0xffffffffu, mx0, 2));
        mx1 = fmaxf(mx1, __shfl_xor_sync(0xffffffffu, mx1, 1));
        mx1 = fmaxf(mx1, __shfl_xor_sync(0xffffffffu, mx1, 2));

        float mn0 = fmaxf(m0, mx0);
        float mn1 = fmaxf(m1, mx1);
        float sc0 = __expf(m0 - mn0);
        float sc1 = __expf(m1 - mn1);
        m0 = mn0; m1 = mn1;

        float ps[8][4];
        float rs0 = 0.f, rs1 = 0.f;
#pragma unroll
        for (int nt = 0; nt < 8; nt++) {
            ps[nt][0] = __expf(Sf[nt][0] - mn0);
            ps[nt][1] = __expf(Sf[nt][1] - mn0);
            ps[nt][2] = __expf(Sf[nt][2] - mn1);
            ps[nt][3] = __expf(Sf[nt][3] - mn1);
            rs0 += ps[nt][0] + ps[nt][1];
            rs1 += ps[nt][2] + ps[nt][3];
        }
        rs0 += __shfl_xor_sync(0xffffffffu, rs0, 1);
        rs0 += __shfl_xor_sync(0xffffffffu, rs0, 2);
        rs1 += __shfl_xor_sync(0xffffffffu, rs1, 1);
        rs1 += __shfl_xor_sync(0xffffffffu, rs1, 2);
        l0 = l0 * sc0 + rs0;
        l1 = l1 * sc1 + rs1;

#pragma unroll
        for (int nt = 0; nt < 16; nt++) {
            Oacc[nt][0] *= sc0; Oacc[nt][1] *= sc0;
            Oacc[nt][2] *= sc1; Oacc[nt][3] *= sc1;
        }

        // ---- O += P V : P transposed C-frag -> A-frag via shfl (no smem) ----
#pragma unroll
        for (int kt = 0; kt < 8; kt++) {
            float e0 = __shfl_sync(0xffffffffu, ps[kt][0], src0);
            float e1 = __shfl_sync(0xffffffffu, ps[kt][1], src0);
            float e2 = __shfl_sync(0xffffffffu, ps[kt][2], src0);
            float e3 = __shfl_sync(0xffffffffu, ps[kt][3], src0);
            float f0 = __shfl_sync(0xffffffffu, ps[kt][0], src1);
            float f1 = __shfl_sync(0xffffffffu, ps[kt][1], src1);
            float f2 = __shfl_sync(0xffffffffu, ps[kt][2], src1);
            float f3 = __shfl_sync(0xffffffffu, ps[kt][3], src1);
            unsigned Pa[4];
            Pa[0] = f2tf(odd ? e1 : e0);   // P[rl   ][8kt+cl]
            Pa[1] = f2tf(odd ? e3 : e2);   // P[rl+8 ][8kt+cl]
            Pa[2] = f2tf(odd ? f1 : f0);   // P[rl   ][8kt+4+cl]
            Pa[3] = f2tf(odd ? f3 : f2);   // P[rl+8 ][8kt+4+cl]
#pragma unroll
            for (int nt = 0; nt < 16; nt++) {
                float v0 = Vr[(kt * 8 + cl)     * KSTRW + nt * 8 + rl];
                float v1 = Vr[(kt * 8 + 4 + cl) * KSTRW + nt * 8 + rl];
                mma8(Oacc[nt], Pa, f2tf(v0), f2tf(v1));
            }
        }

        __syncthreads();      // all warps finished PV(kb); Vbuf free

        // ---- issue cp.async V(kb+1) into the single V buffer ----
        if (kb + 1 < ntiles) {
            const float* vp = vg + (size_t)(kb + 1) * 64 * D_;
            unsigned vb32 = smem_base + (unsigned)VR_OFF * 4;
#pragma unroll
            for (int j = 0; j < 16; j++) {
                int i = t + 128 * j;
                int row = i >> 5;
                int c4  = (i & 31) * 4;
                cpa16(vb32 + (unsigned)(row * KSTRW + c4) * 4, vp + (size_t)row * D_ + c4);
            }
            cpa_commit();
        }
    }

    // ---- epilogue: normalize, write ctx[b][l][h][e] ----
    float inv0 = 1.f / l0;
    float inv1 = 1.f / l1;
    const int b = bh >> 2;
    const int h = bh & 3;
    float* dst0 = g_ctx + ((size_t)(b * L_ + qt * 64 + w * 16 + rl))     * (H_ * D_) + h * D_ + 2 * cl;
    float* dst1 = g_ctx + ((size_t)(b * L_ + qt * 64 + w * 16 + 8 + rl)) * (H_ * D_) + h * D_ + 2 * cl;
#pragma unroll
    for (int nt = 0; nt < 16; nt++) {
        float2 o0; o0.x = Oacc[nt][0] * inv0; o0.y = Oacc[nt][1] * inv0;
        float2 o1; o1.x = Oacc[nt][2] * inv1; o1.y = Oacc[nt][3] * inv1;
        *(float2*)(dst0 + nt * 8) = o0;
        *(float2*)(dst1 + nt * 8) = o1;
    }
}

// ---------------------------------------------------------------------------
// Kernel 3: output projection (unchanged from R10).  CTA tile 64m x 64n.
// ---------------------------------------------------------------------------
__global__ __launch_bounds__(256, 2) void wo_kernel(
    const float* __restrict__ Wo,
    float* __restrict__ y)
{
    extern __shared__ unsigned gsm[];
    unsigned* As = gsm;               // 64 * 132
    unsigned* Bs = As + 64 * GSTR;    // 64 * 132

    const int t    = threadIdx.x;
    const int w    = t >> 5;
    const int lane = t & 31;
    const int rl   = lane >> 2;
    const int cl   = lane & 3;
    const int wm   = w & 3;
    const int wn   = w >> 2;
    const int m0   = blockIdx.x * 64;
    const int n0   = blockIdx.y * 64;

    float acc[4][4];
#pragma unroll
    for (int nt = 0; nt < 4; nt++)
#pragma unroll
        for (int c = 0; c < 4; c++) acc[nt][c] = 0.f;

    for (int kc = 0; kc < H_ * D_; kc += 128) {
        __syncthreads();
        for (int i = t; i < 2048; i += 256) {
            int row = i >> 5;
            int c4  = (i & 31) * 4;
            int base = row * GSTR + ((c4 >> 6) << 6) + (((c4 >> 2) & 1) << 5) + ((c4 >> 3) & 7);
            float4 av = *(const float4*)(g_ctx + (size_t)(m0 + row) * (H_ * D_) + kc + c4);
            As[base]      = f2tf(av.x);
            As[base + 8]  = f2tf(av.y);
            As[base + 16] = f2tf(av.z);
            As[base + 24] = f2tf(av.w);
            float4 wv = *(const float4*)(Wo + (size_t)(n0 + row) * (H_ * D_) + kc + c4);
            Bs[base]      = f2tf(wv.x);
            Bs[base + 8]  = f2tf(wv.y);
            Bs[base + 16] = f2tf(wv.z);
            Bs[base + 24] = f2tf(wv.w);
        }
        __syncthreads();

#pragma unroll
        for (int ktg = 0; ktg < 4; ktg++) {
            const int kbase = ((ktg >> 1) << 6) + ((ktg & 1) << 2) + cl * 8;
            int ar = (wm * 16 + rl) * GSTR + kbase;
            uint4 a0 = *(const uint4*)&As[ar];
            uint4 a2 = *(const uint4*)&As[ar + 32];
            uint4 a1 = *(const uint4*)&As[ar + 8 * GSTR];
            uint4 a3 = *(const uint4*)&As[ar + 8 * GSTR + 32];
#pragma unroll
            for (int nt = 0; nt < 4; nt++) {
                int br = (wn * 32 + nt * 8 + rl) * GSTR + kbase;
                uint4 b0 = *(const uint4*)&Bs[br];
                uint4 b1 = *(const uint4*)&Bs[br + 32];
                unsigned aa[4];
                aa[0] = a0.x; aa[1] = a1.x; aa[2] = a2.x; aa[3] = a3.x;
                mma8(acc[nt], aa, b0.x, b1.x);
                aa[0] = a0.y; aa[1] = a1.y; aa[2] = a2.y; aa[3] = a3.y;
                mma8(acc[nt], aa, b0.y, b1.y);
                aa[0] = a0.z; aa[1] = a1.z; aa[2] = a2.z; aa[3] = a3.z;
                mma8(acc[nt], aa, b0.z, b1.z);
                aa[0] = a0.w; aa[1] = a1.w; aa[2] = a2.w; aa[3] = a3.w;
                mma8(acc[nt], aa, b0.w, b1.w);
            }
        }
    }

    int m = m0 + wm * 16 + rl;
#pragma unroll
    for (int nt = 0; nt < 4; nt++) {
        int n = n0 + wn * 32 + nt * 8 + 2 * cl;
        float2 lo; lo.x = acc[nt][0]; lo.y = acc[nt][1];
        float2 hi; hi.x = acc[nt][2]; hi.y = acc[nt][3];
        *(float2*)(y + (size_t)m * D_ + n) = lo;
        *(float2*)(y + (size_t)(m + 8) * D_ + n) = hi;
    }
}

// ---------------------------------------------------------------------------
extern "C" void kernel_launch(void* const* d_in, const int* in_sizes, int n_in,
                              void* d_out, int out_size)
{
    const float* x  = (const float*)d_in[0];
    const float* Wq = (const float*)d_in[1];
    const float* Wk = (const float*)d_in[2];
    const float* Wv = (const float*)d_in[3];
    const float* Wo = (const float*)d_in[4];
    float* y = (float*)d_out;

    const int attn_smem = SM_WORDS * (int)sizeof(unsigned);                  // 104,448 B
    const int qkv_smem  = (128 * GSTR + 64 * GSTR) * (int)sizeof(unsigned);  // 101,376 B
    const int wo_smem   = (2 * 64 * GSTR) * (int)sizeof(unsigned);           // 67,584 B
    cudaFuncSetAttribute(attn_kernel, cudaFuncAttributeMaxDynamicSharedMemorySize, attn_smem);
    cudaFuncSetAttribute(qkv_kernel,  cudaFuncAttributeMaxDynamicSharedMemorySize, qkv_smem);
    cudaFuncSetAttribute(wo_kernel,   cudaFuncAttributeMaxDynamicSharedMemorySize, wo_smem);

    // 1) QKV projections (tf32 tensor, 2 CTAs/SM)
    {
        dim3 grid((B_ * L_) / 128, (H_ * D_) / 64, 3);
        qkv_kernel<<<grid, 256, qkv_smem>>>(x, Wq, Wk, Wv);
    }
    // 2) Causal flash attention (tf32 tensor, 2 CTAs/SM, Q-tile 64)
    {
        dim3 grid(L_ / 64, B_ * H_);
        attn_kernel<<<grid, 128, attn_smem>>>();
    }
    // 3) Output projection (tf32 tensor, 256 CTAs)
    {
        dim3 grid((B_ * L_) / 64, D_ / 64);
        wo_kernel<<<grid, 256, wo_smem>>>(Wo, y);
    }
}

// round 14
// speedup vs baseline: 1.0916x; 1.0916x over previous
#include <cuda_runtime.h>
#include <math.h>

// Problem constants
#define B_  2
#define L_  4096
#define D_  128
#define H_  4

// Scratch (allocation-free rule: __device__ globals)
__device__ float g_q[B_ * H_ * L_ * D_];
__device__ float g_k[B_ * H_ * L_ * D_];
__device__ float g_v[B_ * H_ * L_ * D_];
__device__ float g_ctx[B_ * L_ * H_ * D_];   // [b][l][h][e]

// ---------------------------------------------------------------------------
// tf32 helpers
// ---------------------------------------------------------------------------
__device__ __forceinline__ unsigned f2tf(float f) {
    unsigned r;
    asm("cvt.rna.tf32.f32 %0, %1;" : "=r"(r) : "f"(f));
    return r;
}

__device__ __forceinline__ void mma8(float d[4], const unsigned a[4],
                                     unsigned b0, unsigned b1) {
    asm volatile(
        "mma.sync.aligned.m16n8k8.row.col.f32.tf32.tf32.f32 "
        "{%0,%1,%2,%3}, {%4,%5,%6,%7}, {%8,%9}, {%0,%1,%2,%3};\n"
        : "+f"(d[0]), "+f"(d[1]), "+f"(d[2]), "+f"(d[3])
        : "r"(a[0]), "r"(a[1]), "r"(a[2]), "r"(a[3]), "r"(b0), "r"(b1));
}

__device__ __forceinline__ void cpa16(unsigned saddr, const void* g) {
    asm volatile("cp.async.cg.shared.global [%0], [%1], 16;"
                 :: "r"(saddr), "l"(g));
}
__device__ __forceinline__ void cpa_commit() {
    asm volatile("cp.async.commit_group;");
}
__device__ __forceinline__ void cpa_wait0() {
    asm volatile("cp.async.wait_group 0;");
}
__device__ __forceinline__ void pair_bar(int id) {
    asm volatile("bar.sync %0, 64;" :: "r"(id) : "memory");
}

// pi_128 permutation (GEMM staging): element c -> base + {0,8,16,24} within
//   base = (c>>6)*64 + ((c>>2)&1)*32 + ((c>>3)&7)
#define GSTR 132

// ---------------------------------------------------------------------------
// Kernel 1: QKV projections (unchanged from R10).  CTA tile 128m x 64n.
// ---------------------------------------------------------------------------
__global__ __launch_bounds__(256, 2) void qkv_kernel(
    const float* __restrict__ x,
    const float* __restrict__ Wq,
    const float* __restrict__ Wk,
    const float* __restrict__ Wv)
{
    extern __shared__ unsigned gsm[];
    unsigned* As = gsm;                // 128 * 132
    unsigned* Bs = As + 128 * GSTR;    // 64  * 132

    const float* W   = (blockIdx.z == 0) ? Wq : ((blockIdx.z == 1) ? Wk : Wv);
    float*       out = (blockIdx.z == 0) ? g_q : ((blockIdx.z == 1) ? g_k : g_v);

    const int t    = threadIdx.x;
    const int w    = t >> 5;
    const int lane = t & 31;
    const int rl   = lane >> 2;
    const int cl   = lane & 3;
    const int wm   = w & 3;
    const int wn   = w >> 2;
    const int m0   = blockIdx.x * 128;
    const int n0   = blockIdx.y * 64;

    for (int i = t; i < 4096; i += 256) {
        int row = i >> 5;
        int c4  = (i & 31) * 4;
        int base = row * GSTR + ((c4 >> 6) << 6) + (((c4 >> 2) & 1) << 5) + ((c4 >> 3) & 7);
        float4 xv = *(const float4*)(x + (size_t)(m0 + row) * D_ + c4);
        As[base]      = f2tf(xv.x);
        As[base + 8]  = f2tf(xv.y);
        As[base + 16] = f2tf(xv.z);
        As[base + 24] = f2tf(xv.w);
    }
    for (int i = t; i < 2048; i += 256) {
        int row = i >> 5;
        int c4  = (i & 31) * 4;
        int base = row * GSTR + ((c4 >> 6) << 6) + (((c4 >> 2) & 1) << 5) + ((c4 >> 3) & 7);
        float4 wv = *(const float4*)(W + (size_t)(n0 + row) * D_ + c4);
        Bs[base]      = f2tf(wv.x);
        Bs[base + 8]  = f2tf(wv.y);
        Bs[base + 16] = f2tf(wv.z);
        Bs[base + 24] = f2tf(wv.w);
    }
    __syncthreads();

    float acc[2][4][4];
#pragma unroll
    for (int mt = 0; mt < 2; mt++)
#pragma unroll
        for (int nt = 0; nt < 4; nt++)
#pragma unroll
            for (int c = 0; c < 4; c++) acc[mt][nt][c] = 0.f;

#pragma unroll
    for (int ktg = 0; ktg < 4; ktg++) {
        const int kbase = ((ktg >> 1) << 6) + ((ktg & 1) << 2) + cl * 8;
        uint4 a0[2], a1[2], a2[2], a3[2];
#pragma unroll
        for (int mt = 0; mt < 2; mt++) {
            int ar = (wm * 32 + mt * 16 + rl) * GSTR + kbase;
            a0[mt] = *(const uint4*)&As[ar];
            a2[mt] = *(const uint4*)&As[ar + 32];
            a1[mt] = *(const uint4*)&As[ar + 8 * GSTR];
            a3[mt] = *(const uint4*)&As[ar + 8 * GSTR + 32];
        }
#pragma unroll
        for (int nt = 0; nt < 4; nt++) {
            int br = (wn * 32 + nt * 8 + rl) * GSTR + kbase;
            uint4 b0 = *(const uint4*)&Bs[br];
            uint4 b1 = *(const uint4*)&Bs[br + 32];
#pragma unroll
            for (int mt = 0; mt < 2; mt++) {
                unsigned aa[4];
                aa[0] = a0[mt].x; aa[1] = a1[mt].x; aa[2] = a2[mt].x; aa[3] = a3[mt].x;
                mma8(acc[mt][nt], aa, b0.x, b1.x);
                aa[0] = a0[mt].y; aa[1] = a1[mt].y; aa[2] = a2[mt].y; aa[3] = a3[mt].y;
                mma8(acc[mt][nt], aa, b0.y, b1.y);
                aa[0] = a0[mt].z; aa[1] = a1[mt].z; aa[2] = a2[mt].z; aa[3] = a3[mt].z;
                mma8(acc[mt][nt], aa, b0.z, b1.z);
                aa[0] = a0[mt].w; aa[1] = a1[mt].w; aa[2] = a2[mt].w; aa[3] = a3[mt].w;
                mma8(acc[mt][nt], aa, b0.w, b1.w);
            }
        }
    }

    const int h = n0 >> 7;
#pragma unroll
    for (int mt = 0; mt < 2; mt++) {
        int m = m0 + wm * 32 + mt * 16 + rl;
        int b = m >> 12;
        int l = m & 4095;
        float* obase = out + (((size_t)b * H_ + h) * L_ + l) * D_;
#pragma unroll
        for (int nt = 0; nt < 4; nt++) {
            int n = n0 + wn * 32 + nt * 8 + 2 * cl;
            int e = n & 127;
            float2 lo; lo.x = acc[mt][nt][0]; lo.y = acc[mt][nt][1];
            float2 hi; hi.x = acc[mt][nt][2]; hi.y = acc[mt][nt][3];
            *(float2*)(obase + e) = lo;
            *(float2*)(obase + 8 * (size_t)D_ + e) = hi;
        }
    }
}

// ---------------------------------------------------------------------------
// Kernel 2: causal flash attention, tf32, 16 warps/SM (2 CTAs x 256 thr).
// grid = (L/64, B*H).  CTA: Q-tile 64, key-tile 32.
// Warp pair (p, p+4): p = w&3 owns q rows [p*16, p*16+16); half = w>>2 owns
// local keys [half*16, half*16+16) of each tile.  Softmax row stats merged
// via smem exchange + pair barrier; partial O summed once at the end.
// smem (words): Q 64*132 (raw fp32, truncated-as-tf32) | K[2] 32*132 each |
// V 32*136 | Xm 2*64 | Xs 2*64  = 21504 words = 86,016 B -> 2 CTAs/SM.
// ---------------------------------------------------------------------------
#define QS_OFF 0
#define KS_OFF 8448                    // 64*132
#define KBUF   4224                    // 32*132
#define VS_OFF (KS_OFF + 2 * KBUF)     // 16896
#define XM_OFF (VS_OFF + 32 * 136)     // 21248
#define XS_OFF (XM_OFF + 128)          // 21376
#define ATT_WORDS (XS_OFF + 128)       // 21504

__global__ __launch_bounds__(256, 2) void attn_kernel()
{
    extern __shared__ unsigned sm[];
    unsigned smem_base = (unsigned)__cvta_generic_to_shared(sm);

    const int t    = threadIdx.x;
    const int w    = t >> 5;           // 0..7
    const int p    = w & 3;            // pair id: q rows [p*16, p*16+16)
    const int half = w >> 2;           // key half: local keys [half*16, +16)
    const int lane = t & 31;
    const int rl   = lane >> 2;        // 0..7
    const int cl   = lane & 3;         // 0..3
    const int qt   = (gridDim.x - 1) - blockIdx.x;   // heavy tiles first
    const int bh   = blockIdx.y;

    const float* qg = g_q + ((size_t)bh * L_ + (size_t)qt * 64) * D_;
    const float* kg = g_k + (size_t)bh * L_ * D_;
    const float* vg = g_v + (size_t)bh * L_ * D_;

    const int ntiles = 2 * (qt + 1);   // 32-key tiles covering [0, 64*(qt+1))

    // ---- prologue: cp.async Q (64x128), K0 (32x128), V0 (32x128) ----
    {
#pragma unroll
        for (int j = 0; j < 8; j++) {          // Q: 2048 chunks
            int i = t + 256 * j;
            int row = i >> 5;
            int c4  = (i & 31) * 4;
            cpa16(smem_base + (unsigned)(QS_OFF + row * 132 + c4) * 4,
                  qg + (size_t)row * D_ + c4);
        }
#pragma unroll
        for (int j = 0; j < 4; j++) {          // K0 + V0: 1024 chunks each
            int i = t + 256 * j;
            int row = i >> 5;
            int c4  = (i & 31) * 4;
            cpa16(smem_base + (unsigned)(KS_OFF + row * 132 + c4) * 4,
                  kg + (size_t)row * D_ + c4);
            cpa16(smem_base + (unsigned)(VS_OFF + row * 136 + c4) * 4,
                  vg + (size_t)row * D_ + c4);
        }
        cpa_commit();
    }

    float Oacc[16][4];
#pragma unroll
    for (int nt = 0; nt < 16; nt++)
#pragma unroll
        for (int c = 0; c < 4; c++) Oacc[nt][c] = 0.f;
    float m0 = -INFINITY, m1 = -INFINITY, l0 = 0.f, l1 = 0.f;

    const int qg0 = qt * 64 + p * 16 + rl;     // global q row (low)
    const int qg1 = qg0 + 8;
    const int barid = 1 + p;

    const unsigned* Qs = sm + QS_OFF;
    const float*    Vr = (const float*)(sm + VS_OFF);
    float* Xm = (float*)(sm + XM_OFF);         // [2][64] row max per half
    float* Xs = (float*)(sm + XS_OFF);         // [2][64] row sum per half

    const int src0 = 4 * rl + (cl >> 1);       // shfl sources for P transpose
    const int src1 = src0 + 2;
    const bool odd = (cl & 1);

    for (int kb = 0; kb < ntiles; ++kb) {
        cpa_wait0();          // K(kb), V(kb) landed (this thread's groups)
        __syncthreads();      // visible; all warps done with tile kb-1

        const unsigned* Kp = sm + KS_OFF + (kb & 1) * KBUF;

        // ---- prefetch K(kb+1) into the other K buffer ----
        if (kb + 1 < ntiles) {
            const float* kp = kg + (size_t)(kb + 1) * 32 * D_;
            unsigned kb32 = smem_base + (unsigned)(KS_OFF + ((kb + 1) & 1) * KBUF) * 4;
#pragma unroll
            for (int j = 0; j < 4; j++) {
                int i = t + 256 * j;
                int row = i >> 5;
                int c4  = (i & 31) * 4;
                cpa16(kb32 + (unsigned)(row * 132 + c4) * 4, kp + (size_t)row * D_ + c4);
            }
            cpa_commit();
        }

        // ---- S = Q K^T over this warp's 16 keys (nt = 0..1) ----
        float Sf[2][4];
#pragma unroll
        for (int nt = 0; nt < 2; nt++)
#pragma unroll
            for (int c = 0; c < 4; c++) Sf[nt][c] = 0.f;

#pragma unroll
        for (int kt = 0; kt < 16; kt++) {
            unsigned a[4];
            a[0] = Qs[(p * 16 + rl)     * 132 + kt * 8 + cl];
            a[1] = Qs[(p * 16 + 8 + rl) * 132 + kt * 8 + cl];
            a[2] = Qs[(p * 16 + rl)     * 132 + kt * 8 + 4 + cl];
            a[3] = Qs[(p * 16 + 8 + rl) * 132 + kt * 8 + 4 + cl];
#pragma unroll
            for (int nt = 0; nt < 2; nt++) {
                int krow = half * 16 + nt * 8 + rl;
                unsigned b0 = Kp[krow * 132 + kt * 8 + cl];
                unsigned b1 = Kp[krow * 132 + kt * 8 + 4 + cl];
                mma8(Sf[nt], a, b0, b1);
            }
        }

        // ---- causal mask (last two tiles) ----
        if (kb >= 2 * qt) {
#pragma unroll
            for (int nt = 0; nt < 2; nt++) {
                int kgb = kb * 32 + half * 16 + nt * 8 + 2 * cl;
                if (kgb     > qg0) Sf[nt][0] = -INFINITY;
                if (kgb + 1 > qg0) Sf[nt][1] = -INFINITY;
                if (kgb     > qg1) Sf[nt][2] = -INFINITY;
                if (kgb + 1 > qg1) Sf[nt][3] = -INFINITY;
            }
        }

        // ---- softmax: per-warp row max over 16 keys, merged across pair ----
        float mx0 = fmaxf(fmaxf(Sf[0][0], Sf[0][1]), fmaxf(Sf[1][0], Sf[1][1]));
        float mx1 = fmaxf(fmaxf(Sf[0][2], Sf[0][3]), fmaxf(Sf[1][2], Sf[1][3]));
        mx0 = fmaxf(mx0, __shfl_xor_sync(0xffffffffu, mx0, 1));
        mx0 = fmaxf(mx0, __shfl_xor_sync(0xffffffffu, mx0, 2));
        mx1 = fmaxf(mx1, __shfl_xor_sync(0xffffffffu, mx1, 1));
        mx1 = fmaxf(mx1, __shfl_xor_sync(0xffffffffu, mx1, 2));
        if (cl == 0) {
            Xm[half * 64 + p * 16 + rl]     = mx0;
            Xm[half * 64 + p * 16 + 8 + rl] = mx1;
        }
        pair_bar(barid);
        float tm0 = fmaxf(mx0, Xm[(1 - half) * 64 + p * 16 + rl]);
        float tm1 = fmaxf(mx1, Xm[(1 - half) * 64 + p * 16 + 8 + rl]);

        float mn0 = fmaxf(m0, tm0);
        float mn1 = fmaxf(m1, tm1);
        float sc0 = __expf(m0 - mn0);
        float sc1 = __expf(m1 - mn1);
        m0 = mn0; m1 = mn1;

        float ps[2][4];
        float rs0 = 0.f, rs1 = 0.f;
#pragma unroll
        for (int nt = 0; nt < 2; nt++) {
            ps[nt][0] = __expf(Sf[nt][0] - mn0);
            ps[nt][1] = __expf(Sf[nt][1] - mn0);
            ps[nt][2] = __expf(Sf[nt][2] - mn1);
            ps[nt][3] = __expf(Sf[nt][3] - mn1);
            rs0 += ps[nt][0] + ps[nt][1];
            rs1 += ps[nt][2] + ps[nt][3];
        }
        rs0 += __shfl_xor_sync(0xffffffffu, rs0, 1);
        rs0 += __shfl_xor_sync(0xffffffffu, rs0, 2);
        rs1 += __shfl_xor_sync(0xffffffffu, rs1, 1);
        rs1 += __shfl_xor_sync(0xffffffffu, rs1, 2);
        if (cl == 0) {
            Xs[half * 64 + p * 16 + rl]     = rs0;
            Xs[half * 64 + p * 16 + 8 + rl] = rs1;
        }
        pair_bar(barid);
        float to0 = Xs[(1 - half) * 64 + p * 16 + rl];
        float to1 = Xs[(1 - half) * 64 + p * 16 + 8 + rl];
        l0 = l0 * sc0 + rs0 + to0;
        l1 = l1 * sc1 + rs1 + to1;

#pragma unroll
        for (int nt = 0; nt < 16; nt++) {
            Oacc[nt][0] *= sc0; Oacc[nt][1] *= sc0;
            Oacc[nt][2] *= sc1; Oacc[nt][3] *= sc1;
        }

        // ---- O += P V over this warp's 16 keys (kt2 = 0..1) ----
#pragma unroll
        for (int kt2 = 0; kt2 < 2; kt2++) {
            float e0 = __shfl_sync(0xffffffffu, ps[kt2][0], src0);
            float e1 = __shfl_sync(0xffffffffu, ps[kt2][1], src0);
            float e2 = __shfl_sync(0xffffffffu, ps[kt2][2], src0);
            float e3 = __shfl_sync(0xffffffffu, ps[kt2][3], src0);
            float f0 = __shfl_sync(0xffffffffu, ps[kt2][0], src1);
            float f1 = __shfl_sync(0xffffffffu, ps[kt2][1], src1);
            float f2 = __shfl_sync(0xffffffffu, ps[kt2][2], src1);
            float f3 = __shfl_sync(0xffffffffu, ps[kt2][3], src1);
            unsigned Pa[4];
            Pa[0] = f2tf(odd ? e1 : e0);
            Pa[1] = f2tf(odd ? e3 : e2);
            Pa[2] = f2tf(odd ? f1 : f0);
            Pa[3] = f2tf(odd ? f3 : f2);
            const int kbase = half * 16 + kt2 * 8;
#pragma unroll
            for (int nt = 0; nt < 16; nt++) {
                float v0 = Vr[(kbase + cl)     * 136 + nt * 8 + rl];
                float v1 = Vr[(kbase + 4 + cl) * 136 + nt * 8 + rl];
                mma8(Oacc[nt], Pa, f2tf(v0), f2tf(v1));
            }
        }

        __syncthreads();      // all warps finished reading V(kb)

        // ---- issue V(kb+1) into the single V buffer ----
        if (kb + 1 < ntiles) {
            const float* vp = vg + (size_t)(kb + 1) * 32 * D_;
            unsigned vb32 = smem_base + (unsigned)VS_OFF * 4;
#pragma unroll
            for (int j = 0; j < 4; j++) {
                int i = t + 256 * j;
                int row = i >> 5;
                int c4  = (i & 31) * 4;
                cpa16(vb32 + (unsigned)(row * 136 + c4) * 4, vp + (size_t)row * D_ + c4);
            }
            cpa_commit();
        }
    }

    // ---- merge pair partials: half 1 dumps Oacc, half 0 sums + writes ----
    __syncthreads();
    float* Xo = (float*)sm;   // reuse Q/K region: 4 pairs x 16 x 128 = 8192 words
    if (half == 1) {
#pragma unroll
        for (int nt = 0; nt < 16; nt++) {
            float* d0 = Xo + p * 2048 + (rl)     * 128 + nt * 8 + 2 * cl;
            float* d1 = Xo + p * 2048 + (8 + rl) * 128 + nt * 8 + 2 * cl;
            d0[0] = Oacc[nt][0]; d0[1] = Oacc[nt][1];
            d1[0] = Oacc[nt][2]; d1[1] = Oacc[nt][3];
        }
    }
    __syncthreads();
    if (half == 0) {
        float inv0 = 1.f / l0;
        float inv1 = 1.f / l1;
        const int b = bh >> 2;
        const int h = bh & 3;
        float* dst0 = g_ctx + ((size_t)(b * L_ + qt * 64 + p * 16 + rl))     * (H_ * D_) + h * D_ + 2 * cl;
        float* dst1 = g_ctx + ((size_t)(b * L_ + qt * 64 + p * 16 + 8 + rl)) * (H_ * D_) + h * D_ + 2 * cl;
#pragma unroll
        for (int nt = 0; nt < 16; nt++) {
            const float* s0 = Xo + p * 2048 + (rl)     * 128 + nt * 8 + 2 * cl;
            const float* s1 = Xo + p * 2048 + (8 + rl) * 128 + nt * 8 + 2 * cl;
            float2 o0, o1;
            o0.x = (Oacc[nt][0] + s0[0]) * inv0;
            o0.y = (Oacc[nt][1] + s0[1]) * inv0;
            o1.x = (Oacc[nt][2] + s1[0]) * inv1;
            o1.y = (Oacc[nt][3] + s1[1]) * inv1;
            *(float2*)(dst0 + nt * 8) = o0;
            *(float2*)(dst1 + nt * 8) = o1;
        }
    }
}

// ---------------------------------------------------------------------------
// Kernel 3: output projection (unchanged from R10).  CTA tile 64m x 64n.
// ---------------------------------------------------------------------------
__global__ __launch_bounds__(256, 2) void wo_kernel(
    const float* __restrict__ Wo,
    float* __restrict__ y)
{
    extern __shared__ unsigned gsm[];
    unsigned* As = gsm;               // 64 * 132
    unsigned* Bs = As + 64 * GSTR;    // 64 * 132

    const int t    = threadIdx.x;
    const int w    = t >> 5;
    const int lane = t & 31;
    const int rl   = lane >> 2;
    const int cl   = lane & 3;
    const int wm   = w & 3;
    const int wn   = w >> 2;
    const int m0   = blockIdx.x * 64;
    const int n0   = blockIdx.y * 64;

    float acc[4][4];
#pragma unroll
    for (int nt = 0; nt < 4; nt++)
#pragma unroll
        for (int c = 0; c < 4; c++) acc[nt][c] = 0.f;

    for (int kc = 0; kc < H_ * D_; kc += 128) {
        __syncthreads();
        for (int i = t; i < 2048; i += 256) {
            int row = i >> 5;
            int c4  = (i & 31) * 4;
            int base = row * GSTR + ((c4 >> 6) << 6) + (((c4 >> 2) & 1) << 5) + ((c4 >> 3) & 7);
            float4 av = *(const float4*)(g_ctx + (size_t)(m0 + row) * (H_ * D_) + kc + c4);
            As[base]      = f2tf(av.x);
            As[base + 8]  = f2tf(av.y);
            As[base + 16] = f2tf(av.z);
            As[base + 24] = f2tf(av.w);
            float4 wv = *(const float4*)(Wo + (size_t)(n0 + row) * (H_ * D_) + kc + c4);
            Bs[base]      = f2tf(wv.x);
            Bs[base + 8]  = f2tf(wv.y);
            Bs[base + 16] = f2tf(wv.z);
            Bs[base + 24] = f2tf(wv.w);
        }
        __syncthreads();

#pragma unroll
        for (int ktg = 0; ktg < 4; ktg++) {
            const int kbase = ((ktg >> 1) << 6) + ((ktg & 1) << 2) + cl * 8;
            int ar = (wm * 16 + rl) * GSTR + kbase;
            uint4 a0 = *(const uint4*)&As[ar];
            uint4 a2 = *(const uint4*)&As[ar + 32];
            uint4 a1 = *(const uint4*)&As[ar + 8 * GSTR];
            uint4 a3 = *(const uint4*)&As[ar + 8 * GSTR + 32];
#pragma unroll
            for (int nt = 0; nt < 4; nt++) {
                int br = (wn * 32 + nt * 8 + rl) * GSTR + kbase;
                uint4 b0 = *(const uint4*)&Bs[br];
                uint4 b1 = *(const uint4*)&Bs[br + 32];
                unsigned aa[4];
                aa[0] = a0.x; aa[1] = a1.x; aa[2] = a2.x; aa[3] = a3.x;
                mma8(acc[nt], aa, b0.x, b1.x);
                aa[0] = a0.y; aa[1] = a1.y; aa[2] = a2.y; aa[3] = a3.y;
                mma8(acc[nt], aa, b0.y, b1.y);
                aa[0] = a0.z; aa[1] = a1.z; aa[2] = a2.z; aa[3] = a3.z;
                mma8(acc[nt], aa, b0.z, b1.z);
                aa[0] = a0.w; aa[1] = a1.w; aa[2] = a2.w; aa[3] = a3.w;
                mma8(acc[nt], aa, b0.w, b1.w);
            }
        }
    }

    int m = m0 + wm * 16 + rl;
#pragma unroll
    for (int nt = 0; nt < 4; nt++) {
        int n = n0 + wn * 32 + nt * 8 + 2 * cl;
        float2 lo; lo.x = acc[nt][0]; lo.y = acc[nt][1];
        float2 hi; hi.x = acc[nt][2]; hi.y = acc[nt][3];
        *(float2*)(y + (size_t)m * D_ + n) = lo;
        *(float2*)(y + (size_t)(m + 8) * D_ + n) = hi;
    }
}

// ---------------------------------------------------------------------------
extern "C" void kernel_launch(void* const* d_in, const int* in_sizes, int n_in,
                              void* d_out, int out_size)
{
    const float* x  = (const float*)d_in[0];
    const float* Wq = (const float*)d_in[1];
    const float* Wk = (const float*)d_in[2];
    const float* Wv = (const float*)d_in[3];
    const float* Wo = (const float*)d_in[4];
    float* y = (float*)d_out;

    const int attn_smem = ATT_WORDS * (int)sizeof(unsigned);                 // 86,016 B
    const int qkv_smem  = (128 * GSTR + 64 * GSTR) * (int)sizeof(unsigned);  // 101,376 B
    const int wo_smem   = (2 * 64 * GSTR) * (int)sizeof(unsigned);           // 67,584 B
    cudaFuncSetAttribute(attn_kernel, cudaFuncAttributeMaxDynamicSharedMemorySize, attn_smem);
    cudaFuncSetAttribute(qkv_kernel,  cudaFuncAttributeMaxDynamicSharedMemorySize, qkv_smem);
    cudaFuncSetAttribute(wo_kernel,   cudaFuncAttributeMaxDynamicSharedMemorySize, wo_smem);

    // 1) QKV projections (tf32 tensor, 2 CTAs/SM)
    {
        dim3 grid((B_ * L_) / 128, (H_ * D_) / 64, 3);
        qkv_kernel<<<grid, 256, qkv_smem>>>(x, Wq, Wk, Wv);
    }
    // 2) Causal flash attention (tf32 tensor, 16 warps/SM, key-split pairs)
    {
        dim3 grid(L_ / 64, B_ * H_);
        attn_kernel<<<grid, 256, attn_smem>>>();
    }
    // 3) Output projection (tf32 tensor, 256 CTAs)
    {
        dim3 grid((B_ * L_) / 64, D_ / 64);
        wo_kernel<<<grid, 256, wo_smem>>>(Wo, y);
    }
}